// round 1
// baseline (speedup 1.0000x reference)
#include <cuda_runtime.h>

// Problem constants
#define NQPTS 4096
#define HID   1024
#define RR    4096   // R*K = R*R = 64*64
#define NPTS  16384

// ---------------- scratch (device globals; no allocation allowed) ----------
__device__ __align__(16) float g_part[2][64][HID];   // per-block partial t-sums
__device__ float g_ysum[2][64];                      // per-block partial y-sums
__device__ __align__(16) float g_Spart[2][8][RR];    // h-chunked partial S
__device__ __align__(16) float g_r[RR];              // rhs flattened [64*64]
__device__ __align__(16) float g_v[HID];             // Wx2 @ r
__device__ float g_c;                                // bx2 . r

__device__ __forceinline__ float tanh_fast(float x) {
    float y;
    asm("tanh.approx.f32 %0, %1;" : "=f"(y) : "f"(x));
    return y;
}

// ---------------------------------------------------------------------------
// K1: per quad point i: y_i = exp(-eq*||x||^2); accumulate
//     t[h] += y_i * tanh(x_i . W[:,h] + b[h]) into per-block partials.
// grid: 128 blocks (2 MLPs x 64 sub-blocks of 64 points), 256 threads.
// ---------------------------------------------------------------------------
__global__ void k1_quad(const float* __restrict__ qx0, const float* __restrict__ qx1,
                        const float* __restrict__ Wq0a, const float* __restrict__ bq0a,
                        const float* __restrict__ Wq1a, const float* __restrict__ bq1a,
                        const float* __restrict__ eq)
{
    const int blk = blockIdx.x;
    const int mlp = blk >> 6;
    const int sub = blk & 63;
    const float* __restrict__ qx = mlp ? qx1 : qx0;
    const float* __restrict__ W  = mlp ? Wq1a : Wq0a;
    const float* __restrict__ B  = mlp ? bq1a : bq0a;
    const int P = NQPTS / 64;           // 64 points per block
    const int base = sub * P;
    const int tid = threadIdx.x;

    __shared__ float sx0[64], sx1[64], sx2[64], sy[64];
    if (tid < P) {
        float x0 = qx[(base + tid) * 3 + 0];
        float x1 = qx[(base + tid) * 3 + 1];
        float x2 = qx[(base + tid) * 3 + 2];
        sx0[tid] = x0; sx1[tid] = x1; sx2[tid] = x2;
        sy[tid]  = __expf(-eq[0] * (x0 * x0 + x1 * x1 + x2 * x2));
    }
    __syncthreads();

    float w0[4], w1[4], w2[4], bb[4], acc[4];
#pragma unroll
    for (int k = 0; k < 4; k++) {
        int h = tid + 256 * k;
        w0[k] = W[h]; w1[k] = W[HID + h]; w2[k] = W[2 * HID + h];
        bb[k] = B[h];
        acc[k] = 0.0f;
    }
    for (int p = 0; p < P; p++) {
        float x0 = sx0[p], x1 = sx1[p], x2 = sx2[p], y = sy[p];
#pragma unroll
        for (int k = 0; k < 4; k++) {
            float a = fmaf(x0, w0[k], fmaf(x1, w1[k], fmaf(x2, w2[k], bb[k])));
            acc[k] = fmaf(y, tanh_fast(a), acc[k]);
        }
    }
#pragma unroll
    for (int k = 0; k < 4; k++)
        g_part[mlp][sub][tid + 256 * k] = acc[k];
    if (tid == 0) {
        float s = 0.0f;
        for (int p = 0; p < P; p++) s += sy[p];
        g_ysum[mlp][sub] = s;
    }
}

// ---------------------------------------------------------------------------
// K2: S[j] = sum_h t[h]*Wqb[h,j] + ysum*bqb[j], split into 8 h-chunks of 128.
// grid: 64 blocks (2 MLPs x 8 h-chunks x 4 j-chunks), 256 threads.
// Each thread handles 4 consecutive j (float4 loads) over 128 h.
// ---------------------------------------------------------------------------
__global__ void k2_S(const float* __restrict__ Wq0b, const float* __restrict__ bq0b,
                     const float* __restrict__ Wq1b, const float* __restrict__ bq1b)
{
    const int blk = blockIdx.x;       // 0..63
    const int mlp = blk >> 5;
    const int idx = blk & 31;
    const int jc  = idx & 3;          // 4 chunks of 1024 columns
    const int hc  = idx >> 2;         // 8 chunks of 128 rows
    const float* __restrict__ W = mlp ? Wq1b : Wq0b;
    const float* __restrict__ B = mlp ? bq1b : bq0b;
    const int tid = threadIdx.x;
    const int hbase = hc * 128;

    __shared__ float t[128];
    __shared__ float sys;
    if (tid < 128) {
        float s = 0.0f;
#pragma unroll 8
        for (int b = 0; b < 64; b++) s += g_part[mlp][b][hbase + tid];
        t[tid] = s;
    }
    if (tid == 128) {
        float s = 0.0f;
        for (int b = 0; b < 64; b++) s += g_ysum[mlp][b];
        sys = s;
    }
    __syncthreads();

    const int j0 = jc * 1024 + tid * 4;
    float a0, a1, a2, a3;
    if (hc == 0) {
        float ys = sys;
        a0 = ys * B[j0]; a1 = ys * B[j0 + 1]; a2 = ys * B[j0 + 2]; a3 = ys * B[j0 + 3];
    } else {
        a0 = a1 = a2 = a3 = 0.0f;
    }
    const float4* __restrict__ W4 = (const float4*)W;
    const int col = j0 >> 2;
#pragma unroll 16
    for (int h = 0; h < 128; h++) {
        float th = t[h];
        float4 w = W4[(size_t)(hbase + h) * (RR / 4) + col];
        a0 = fmaf(th, w.x, a0);
        a1 = fmaf(th, w.y, a1);
        a2 = fmaf(th, w.z, a2);
        a3 = fmaf(th, w.w, a3);
    }
    *((float4*)&g_Spart[mlp][hc][j0]) = make_float4(a0, a1, a2, a3);
}

// ---------------------------------------------------------------------------
// K3: rhs[b,d] = sum_x S0[b,x]*S1[d,x]; r = rhs flattened (b*64+d).
// 1 block, 256 threads. Padded smem (pitch 65) for conflict-free reads.
// ---------------------------------------------------------------------------
__global__ void k3_rhs()
{
    __shared__ float s0[64 * 65];
    __shared__ float s1[64 * 65];
    const int tid = threadIdx.x;
#pragma unroll
    for (int k = 0; k < 16; k++) {
        int j = tid + 256 * k;
        float a = 0.0f, b = 0.0f;
#pragma unroll
        for (int hcc = 0; hcc < 8; hcc++) {
            a += g_Spart[0][hcc][j];
            b += g_Spart[1][hcc][j];
        }
        int bb = j >> 6, xx = j & 63;
        s0[bb * 65 + xx] = a;
        s1[bb * 65 + xx] = b;
    }
    __syncthreads();
#pragma unroll
    for (int k = 0; k < 16; k++) {
        int o = k * 256 + tid;
        int b = o >> 6, d = o & 63;
        float acc = 0.0f;
#pragma unroll 8
        for (int x = 0; x < 64; x++)
            acc = fmaf(s0[b * 65 + x], s1[d * 65 + x], acc);
        g_r[o] = acc;
    }
}

// ---------------------------------------------------------------------------
// K4: v[h] = Wx2[h,:] . r (warp per row, float4), and c = bx2 . r.
// grid: 129 blocks x 256 threads (blocks 0..127 -> 8 rows each; block 128 -> c)
// ---------------------------------------------------------------------------
__global__ void k4_v(const float* __restrict__ Wx2, const float* __restrict__ bx2)
{
    const int tid = threadIdx.x;
    __shared__ float4 sr4[RR / 4];
    __shared__ float red[256];
    const float4* __restrict__ gr4 = (const float4*)g_r;
#pragma unroll
    for (int k = 0; k < 4; k++) sr4[tid + 256 * k] = gr4[tid + 256 * k];
    __syncthreads();

    if (blockIdx.x < 128) {
        const int h = blockIdx.x * 8 + (tid >> 5);
        const int lane = tid & 31;
        const float4* __restrict__ Wrow4 = (const float4*)(Wx2 + (size_t)h * RR);
        float acc = 0.0f;
#pragma unroll 8
        for (int it = 0; it < 32; it++) {
            float4 w = Wrow4[it * 32 + lane];
            float4 rr = sr4[it * 32 + lane];
            acc = fmaf(w.x, rr.x, acc);
            acc = fmaf(w.y, rr.y, acc);
            acc = fmaf(w.z, rr.z, acc);
            acc = fmaf(w.w, rr.w, acc);
        }
#pragma unroll
        for (int o = 16; o; o >>= 1) acc += __shfl_xor_sync(0xffffffffu, acc, o);
        if (lane == 0) g_v[h] = acc;
    } else {
        const float4* __restrict__ b4 = (const float4*)bx2;
        float acc = 0.0f;
#pragma unroll
        for (int k = 0; k < 4; k++) {
            float4 b = b4[tid + 256 * k];
            float4 rr = sr4[tid + 256 * k];
            acc += b.x * rr.x + b.y * rr.y + b.z * rr.z + b.w * rr.w;
        }
        red[tid] = acc;
        __syncthreads();
        for (int o = 128; o; o >>= 1) {
            if (tid < o) red[tid] += red[tid + o];
            __syncthreads();
        }
        if (tid == 0) g_c = red[0];
    }
}

// ---------------------------------------------------------------------------
// K5: out[n] = tanh(input[n] @ Wx1 + bx1) . v + c
// grid: 512 blocks x 256 threads; warp handles 4 rows n (reuses smem loads 4x)
// ---------------------------------------------------------------------------
__global__ void k5_out(const float* __restrict__ input, const float* __restrict__ Wx1,
                       const float* __restrict__ bx1, float* __restrict__ out)
{
    __shared__ float4 swb[HID];   // (w0, w1, w2, bias)
    __shared__ float  sv[HID];
    const int tid = threadIdx.x;
#pragma unroll
    for (int k = 0; k < 4; k++) {
        int h = tid + 256 * k;
        swb[h] = make_float4(Wx1[h], Wx1[HID + h], Wx1[2 * HID + h], bx1[h]);
        sv[h] = g_v[h];
    }
    __syncthreads();

    const int warp = tid >> 5, lane = tid & 31;
    const int nbase = (blockIdx.x * 8 + warp) * 4;

    float x0[4], x1[4], x2[4];
#pragma unroll
    for (int nn = 0; nn < 4; nn++) {
        x0[nn] = input[(nbase + nn) * 3 + 0];
        x1[nn] = input[(nbase + nn) * 3 + 1];
        x2[nn] = input[(nbase + nn) * 3 + 2];
    }
    float acc[4] = {0.0f, 0.0f, 0.0f, 0.0f};
#pragma unroll 4
    for (int k = 0; k < 32; k++) {
        int h = k * 32 + lane;
        float4 wb = swb[h];
        float vv = sv[h];
#pragma unroll
        for (int nn = 0; nn < 4; nn++) {
            float a = fmaf(x0[nn], wb.x, fmaf(x1[nn], wb.y, fmaf(x2[nn], wb.z, wb.w)));
            acc[nn] = fmaf(tanh_fast(a), vv, acc[nn]);
        }
    }
    float c = g_c;
#pragma unroll
    for (int nn = 0; nn < 4; nn++) {
        float a = acc[nn];
#pragma unroll
        for (int o = 16; o; o >>= 1) a += __shfl_xor_sync(0xffffffffu, a, o);
        if (lane == 0) out[nbase + nn] = a + c;
    }
}

// ---------------------------------------------------------------------------
// Input order (metadata): 0 input, 1 eq_param, 2 quad_x0, 3 quad_x1,
// 4 Wx1, 5 bx1, 6 Wx2, 7 bx2, 8 Wq0a, 9 bq0a, 10 Wq0b, 11 bq0b,
// 12 Wq1a, 13 bq1a, 14 Wq1b, 15 bq1b
// ---------------------------------------------------------------------------
extern "C" void kernel_launch(void* const* d_in, const int* in_sizes, int n_in,
                              void* d_out, int out_size)
{
    const float* input  = (const float*)d_in[0];
    const float* eq     = (const float*)d_in[1];
    const float* qx0    = (const float*)d_in[2];
    const float* qx1    = (const float*)d_in[3];
    const float* Wx1    = (const float*)d_in[4];
    const float* bx1    = (const float*)d_in[5];
    const float* Wx2    = (const float*)d_in[6];
    const float* bx2    = (const float*)d_in[7];
    const float* Wq0a   = (const float*)d_in[8];
    const float* bq0a   = (const float*)d_in[9];
    const float* Wq0b   = (const float*)d_in[10];
    const float* bq0b   = (const float*)d_in[11];
    const float* Wq1a   = (const float*)d_in[12];
    const float* bq1a   = (const float*)d_in[13];
    const float* Wq1b   = (const float*)d_in[14];
    const float* bq1b   = (const float*)d_in[15];
    float* out = (float*)d_out;

    k1_quad<<<128, 256>>>(qx0, qx1, Wq0a, bq0a, Wq1a, bq1a, eq);
    k2_S<<<64, 256>>>(Wq0b, bq0b, Wq1b, bq1b);
    k3_rhs<<<1, 256>>>();
    k4_v<<<129, 256>>>(Wx2, bx2);
    k5_out<<<512, 256>>>(input, Wx1, bx1, out);
}

// round 2
// speedup vs baseline: 1.0347x; 1.0347x over previous
#include <cuda_runtime.h>

// Problem constants
#define NQPTS 4096
#define HID   1024
#define RR    4096   // R*K = R*R = 64*64
#define NPTS  16384
#define SUBS  128    // k1 sub-blocks per MLP
#define HC    16     // k2 h-chunks (64 rows each)

// ---------------- scratch (device globals; no allocation allowed) ----------
__device__ __align__(16) float g_part[2][SUBS][HID]; // per-block partial t-sums
__device__ float g_ysum[2][SUBS];                    // per-block partial y-sums
__device__ __align__(16) float g_t[2][HID];          // reduced t
__device__ float g_ys[2];                            // reduced y-sum
__device__ __align__(16) float g_Spart[2][HC][RR];   // h-chunked partial S
__device__ __align__(16) float g_S[2][RR];           // reduced S0, S1
__device__ __align__(16) float g_r[RR];              // rhs flattened [64*64]
__device__ __align__(16) float g_v[HID];             // Wx2 @ r
__device__ float g_c;                                // bx2 . r

__device__ __forceinline__ float tanh_fast(float x) {
    float y;
    asm("tanh.approx.f32 %0, %1;" : "=f"(y) : "f"(x));
    return y;
}

// ---------------------------------------------------------------------------
// K1: per quad point i: y_i = exp(-eq*||x||^2); accumulate
//     t[h] += y_i * tanh(x_i . W[:,h] + b[h]) into per-block partials.
// grid: 256 blocks (2 MLPs x 128 sub-blocks of 32 points), 256 threads.
// ---------------------------------------------------------------------------
__global__ void k1_quad(const float* __restrict__ qx0, const float* __restrict__ qx1,
                        const float* __restrict__ Wq0a, const float* __restrict__ bq0a,
                        const float* __restrict__ Wq1a, const float* __restrict__ bq1a,
                        const float* __restrict__ eq)
{
    const int blk = blockIdx.x;
    const int mlp = blk >> 7;
    const int sub = blk & (SUBS - 1);
    const float* __restrict__ qx = mlp ? qx1 : qx0;
    const float* __restrict__ W  = mlp ? Wq1a : Wq0a;
    const float* __restrict__ B  = mlp ? bq1a : bq0a;
    const int P = NQPTS / SUBS;         // 32 points per block
    const int base = sub * P;
    const int tid = threadIdx.x;

    __shared__ float sx0[32], sx1[32], sx2[32], sy[32];
    if (tid < P) {
        float x0 = qx[(base + tid) * 3 + 0];
        float x1 = qx[(base + tid) * 3 + 1];
        float x2 = qx[(base + tid) * 3 + 2];
        sx0[tid] = x0; sx1[tid] = x1; sx2[tid] = x2;
        sy[tid]  = __expf(-eq[0] * (x0 * x0 + x1 * x1 + x2 * x2));
    }
    __syncthreads();

    float w0[4], w1[4], w2[4], bb[4], acc[4];
#pragma unroll
    for (int k = 0; k < 4; k++) {
        int h = tid + 256 * k;
        w0[k] = W[h]; w1[k] = W[HID + h]; w2[k] = W[2 * HID + h];
        bb[k] = B[h];
        acc[k] = 0.0f;
    }
#pragma unroll 4
    for (int p = 0; p < P; p++) {
        float x0 = sx0[p], x1 = sx1[p], x2 = sx2[p], y = sy[p];
#pragma unroll
        for (int k = 0; k < 4; k++) {
            float a = fmaf(x0, w0[k], fmaf(x1, w1[k], fmaf(x2, w2[k], bb[k])));
            acc[k] = fmaf(y, tanh_fast(a), acc[k]);
        }
    }
#pragma unroll
    for (int k = 0; k < 4; k++)
        g_part[mlp][sub][tid + 256 * k] = acc[k];
    if (tid == 0) {
        float s = 0.0f;
#pragma unroll
        for (int p = 0; p < P; p++) s += sy[p];
        g_ysum[mlp][sub] = s;
    }
}

// ---------------------------------------------------------------------------
// K1b: reduce g_part -> g_t (2048 h-values), g_ysum -> g_ys.
// grid: 8 blocks x 256 threads, one h per thread.
// ---------------------------------------------------------------------------
__global__ void k1b_reduce()
{
    const int g = blockIdx.x * 256 + threadIdx.x;   // 0..2047
    const int mlp = g >> 10;
    const int h = g & (HID - 1);
    float s = 0.0f;
#pragma unroll 8
    for (int b = 0; b < SUBS; b++) s += g_part[mlp][b][h];
    g_t[mlp][h] = s;
    if (g < 2) {
        float ys = 0.0f;
#pragma unroll 8
        for (int b = 0; b < SUBS; b++) ys += g_ysum[g][b];
        g_ys[g] = ys;
    }
}

// ---------------------------------------------------------------------------
// K2: Spart[hc][j] = sum_{h in chunk} t[h]*Wqb[h,j]  (+ ys*bqb[j] on hc==0)
// grid: 256 blocks (2 MLPs x 16 h-chunks(64 rows) x 8 j-chunks(512 cols)),
// 128 threads, each thread one float4 column over 64 rows (unroll 8).
// ---------------------------------------------------------------------------
__global__ void k2_S(const float* __restrict__ Wq0b, const float* __restrict__ bq0b,
                     const float* __restrict__ Wq1b, const float* __restrict__ bq1b)
{
    const int blk = blockIdx.x;       // 0..255
    const int mlp = blk >> 7;
    const int rest = blk & 127;
    const int hc = rest >> 3;         // 0..15
    const int jc = rest & 7;          // 0..7
    const float* __restrict__ W = mlp ? Wq1b : Wq0b;
    const float* __restrict__ B = mlp ? bq1b : bq0b;
    const int tid = threadIdx.x;      // 0..127
    const int hbase = hc * 64;

    __shared__ float t[64];
    if (tid < 64) t[tid] = g_t[mlp][hbase + tid];
    __syncthreads();

    const int j0 = jc * 512 + tid * 4;
    float a0, a1, a2, a3;
    if (hc == 0) {
        float ys = g_ys[mlp];
        a0 = ys * B[j0]; a1 = ys * B[j0 + 1]; a2 = ys * B[j0 + 2]; a3 = ys * B[j0 + 3];
    } else {
        a0 = a1 = a2 = a3 = 0.0f;
    }
    const float4* __restrict__ W4 = (const float4*)W;
    const int col = j0 >> 2;
#pragma unroll 8
    for (int h = 0; h < 64; h++) {
        float th = t[h];
        float4 w = W4[(size_t)(hbase + h) * (RR / 4) + col];
        a0 = fmaf(th, w.x, a0);
        a1 = fmaf(th, w.y, a1);
        a2 = fmaf(th, w.z, a2);
        a3 = fmaf(th, w.w, a3);
    }
    *((float4*)&g_Spart[mlp][hc][j0]) = make_float4(a0, a1, a2, a3);
}

// ---------------------------------------------------------------------------
// K2b: reduce g_Spart over hc -> g_S[2][4096].
// grid: 8 blocks x 256 threads, 4 elements each.
// ---------------------------------------------------------------------------
__global__ void k2b_reduce()
{
    const int idx = blockIdx.x * 256 + threadIdx.x;  // 0..2047
#pragma unroll
    for (int m = 0; m < 4; m++) {
        int e = m * 2048 + idx;
        int mlp = e >> 12;
        int j = e & (RR - 1);
        float s = 0.0f;
#pragma unroll
        for (int hc = 0; hc < HC; hc++) s += g_Spart[mlp][hc][j];
        g_S[mlp][j] = s;
    }
}

// ---------------------------------------------------------------------------
// K3: r[b*64+d] = sum_x S0[b,x]*S1[d,x];  c = bx2 . r
// 1 block, 1024 threads. Padded smem for conflict-free reads.
// ---------------------------------------------------------------------------
__global__ void k3_rhs(const float* __restrict__ bx2)
{
    __shared__ float s0[64 * 65];
    __shared__ float s1[64 * 65];
    __shared__ float red[32];
    const int tid = threadIdx.x;   // 0..1023
#pragma unroll
    for (int k = 0; k < 4; k++) {
        int j = k * 1024 + tid;
        int b = j >> 6, x = j & 63;
        s0[b * 65 + x] = g_S[0][j];
        s1[b * 65 + x] = g_S[1][j];
    }
    __syncthreads();
    float cacc = 0.0f;
#pragma unroll
    for (int k = 0; k < 4; k++) {
        int o = k * 1024 + tid;
        int b = o >> 6, d = o & 63;
        float acc = 0.0f;
#pragma unroll 16
        for (int x = 0; x < 64; x++)
            acc = fmaf(s0[b * 65 + x], s1[d * 65 + x], acc);
        g_r[o] = acc;
        cacc = fmaf(acc, bx2[o], cacc);
    }
    // block reduce cacc -> g_c
#pragma unroll
    for (int o = 16; o; o >>= 1) cacc += __shfl_xor_sync(0xffffffffu, cacc, o);
    if ((tid & 31) == 0) red[tid >> 5] = cacc;
    __syncthreads();
    if (tid < 32) {
        float s = red[tid];
#pragma unroll
        for (int o = 16; o; o >>= 1) s += __shfl_xor_sync(0xffffffffu, s, o);
        if (tid == 0) g_c = s;
    }
}

// ---------------------------------------------------------------------------
// K4: v[h] = Wx2[h,:] . r.  grid: 512 blocks x 256 threads, 2 rows per block.
// No smem staging for r (L2-hot broadcast), no pre-barrier.
// ---------------------------------------------------------------------------
__global__ void k4_v(const float* __restrict__ Wx2)
{
    const int h0 = blockIdx.x * 2;
    const int tid = threadIdx.x;
    const float4* __restrict__ W4 = (const float4*)Wx2;
    const float4* __restrict__ r4 = (const float4*)g_r;
    const int c = tid * 4;        // float4 index, 4 per thread (1024 total)

    float a0 = 0.0f, a1 = 0.0f;
#pragma unroll
    for (int k = 0; k < 4; k++) {
        float4 rr = r4[c + k];
        float4 w0 = W4[(size_t)h0 * (RR / 4) + c + k];
        float4 w1 = W4[(size_t)(h0 + 1) * (RR / 4) + c + k];
        a0 = fmaf(w0.x, rr.x, a0); a0 = fmaf(w0.y, rr.y, a0);
        a0 = fmaf(w0.z, rr.z, a0); a0 = fmaf(w0.w, rr.w, a0);
        a1 = fmaf(w1.x, rr.x, a1); a1 = fmaf(w1.y, rr.y, a1);
        a1 = fmaf(w1.z, rr.z, a1); a1 = fmaf(w1.w, rr.w, a1);
    }
#pragma unroll
    for (int o = 16; o; o >>= 1) {
        a0 += __shfl_xor_sync(0xffffffffu, a0, o);
        a1 += __shfl_xor_sync(0xffffffffu, a1, o);
    }
    __shared__ float s0[8], s1[8];
    if ((tid & 31) == 0) { s0[tid >> 5] = a0; s1[tid >> 5] = a1; }
    __syncthreads();
    if (tid == 0) {
        float x = 0.0f, y = 0.0f;
#pragma unroll
        for (int i = 0; i < 8; i++) { x += s0[i]; y += s1[i]; }
        g_v[h0] = x;
        g_v[h0 + 1] = y;
    }
}

// ---------------------------------------------------------------------------
// K5: out[n] = tanh(input[n] @ Wx1 + bx1) . v + c
// grid: 512 blocks x 256 threads; warp handles 4 rows n (reuses smem loads 4x)
// ---------------------------------------------------------------------------
__global__ void k5_out(const float* __restrict__ input, const float* __restrict__ Wx1,
                       const float* __restrict__ bx1, float* __restrict__ out)
{
    __shared__ float4 swb[HID];   // (w0, w1, w2, bias)
    __shared__ float  sv[HID];
    const int tid = threadIdx.x;
#pragma unroll
    for (int k = 0; k < 4; k++) {
        int h = tid + 256 * k;
        swb[h] = make_float4(Wx1[h], Wx1[HID + h], Wx1[2 * HID + h], bx1[h]);
        sv[h] = g_v[h];
    }
    __syncthreads();

    const int warp = tid >> 5, lane = tid & 31;
    const int nbase = (blockIdx.x * 8 + warp) * 4;

    float x0[4], x1[4], x2[4];
#pragma unroll
    for (int nn = 0; nn < 4; nn++) {
        x0[nn] = input[(nbase + nn) * 3 + 0];
        x1[nn] = input[(nbase + nn) * 3 + 1];
        x2[nn] = input[(nbase + nn) * 3 + 2];
    }
    float acc[4] = {0.0f, 0.0f, 0.0f, 0.0f};
#pragma unroll 4
    for (int k = 0; k < 32; k++) {
        int h = k * 32 + lane;
        float4 wb = swb[h];
        float vv = sv[h];
#pragma unroll
        for (int nn = 0; nn < 4; nn++) {
            float a = fmaf(x0[nn], wb.x, fmaf(x1[nn], wb.y, fmaf(x2[nn], wb.z, wb.w)));
            acc[nn] = fmaf(tanh_fast(a), vv, acc[nn]);
        }
    }
    float c = g_c;
#pragma unroll
    for (int nn = 0; nn < 4; nn++) {
        float a = acc[nn];
#pragma unroll
        for (int o = 16; o; o >>= 1) a += __shfl_xor_sync(0xffffffffu, a, o);
        if (lane == 0) out[nbase + nn] = a + c;
    }
}

// ---------------------------------------------------------------------------
// Input order (metadata): 0 input, 1 eq_param, 2 quad_x0, 3 quad_x1,
// 4 Wx1, 5 bx1, 6 Wx2, 7 bx2, 8 Wq0a, 9 bq0a, 10 Wq0b, 11 bq0b,
// 12 Wq1a, 13 bq1a, 14 Wq1b, 15 bq1b
// ---------------------------------------------------------------------------
extern "C" void kernel_launch(void* const* d_in, const int* in_sizes, int n_in,
                              void* d_out, int out_size)
{
    const float* input  = (const float*)d_in[0];
    const float* eq     = (const float*)d_in[1];
    const float* qx0    = (const float*)d_in[2];
    const float* qx1    = (const float*)d_in[3];
    const float* Wx1    = (const float*)d_in[4];
    const float* bx1    = (const float*)d_in[5];
    const float* Wx2    = (const float*)d_in[6];
    const float* bx2    = (const float*)d_in[7];
    const float* Wq0a   = (const float*)d_in[8];
    const float* bq0a   = (const float*)d_in[9];
    const float* Wq0b   = (const float*)d_in[10];
    const float* bq0b   = (const float*)d_in[11];
    const float* Wq1a   = (const float*)d_in[12];
    const float* bq1a   = (const float*)d_in[13];
    const float* Wq1b   = (const float*)d_in[14];
    const float* bq1b   = (const float*)d_in[15];
    float* out = (float*)d_out;

    k1_quad<<<256, 256>>>(qx0, qx1, Wq0a, bq0a, Wq1a, bq1a, eq);
    k1b_reduce<<<8, 256>>>();
    k2_S<<<256, 128>>>(Wq0b, bq0b, Wq1b, bq1b);
    k2b_reduce<<<8, 256>>>();
    k3_rhs<<<1, 1024>>>(bx2);
    k4_v<<<512, 256>>>(Wx2);
    k5_out<<<512, 256>>>(input, Wx1, bx1, out);
}

// round 3
// speedup vs baseline: 1.1975x; 1.1574x over previous
#include <cuda_runtime.h>

// Problem constants
#define NQPTS 4096
#define HID   1024
#define RR    4096   // R*K = R*R = 64*64
#define NPTS  16384
#define SUBS  128    // k1 sub-blocks per MLP
#define HC    16     // k2 h-chunks (64 rows each)

// ---------------- scratch (device globals; no allocation allowed) ----------
__device__ __align__(16) float g_part[2][SUBS][HID]; // per-block partial t-sums
__device__ float g_ysum[2][SUBS];                    // per-block partial y-sums
__device__ __align__(16) float g_Spart[2][HC][RR];   // h-chunked partial S
__device__ __align__(16) float g_r[RR];              // rhs flattened [64*64]
__device__ __align__(16) float g_v[HID];             // Wx2 @ r
__device__ float g_c;                                // bx2 . r

__device__ __forceinline__ float tanh_fast(float x) {
    float y;
    asm("tanh.approx.f32 %0, %1;" : "=f"(y) : "f"(x));
    return y;
}

// ---------------------------------------------------------------------------
// K1: per quad point i: y_i = exp(-eq*||x||^2); accumulate
//     t[h] += y_i * tanh(x_i . W[:,h] + b[h]) into per-block partials.
// grid: 256 blocks (2 MLPs x 128 sub-blocks of 32 points), 256 threads.
// ---------------------------------------------------------------------------
__global__ void k1_quad(const float* __restrict__ qx0, const float* __restrict__ qx1,
                        const float* __restrict__ Wq0a, const float* __restrict__ bq0a,
                        const float* __restrict__ Wq1a, const float* __restrict__ bq1a,
                        const float* __restrict__ eq)
{
    const int blk = blockIdx.x;
    const int mlp = blk >> 7;
    const int sub = blk & (SUBS - 1);
    const float* __restrict__ qx = mlp ? qx1 : qx0;
    const float* __restrict__ W  = mlp ? Wq1a : Wq0a;
    const float* __restrict__ B  = mlp ? bq1a : bq0a;
    const int P = NQPTS / SUBS;         // 32 points per block
    const int base = sub * P;
    const int tid = threadIdx.x;

    __shared__ float sx0[32], sx1[32], sx2[32], sy[32];
    if (tid < P) {
        float x0 = qx[(base + tid) * 3 + 0];
        float x1 = qx[(base + tid) * 3 + 1];
        float x2 = qx[(base + tid) * 3 + 2];
        sx0[tid] = x0; sx1[tid] = x1; sx2[tid] = x2;
        sy[tid]  = __expf(-eq[0] * (x0 * x0 + x1 * x1 + x2 * x2));
    }
    __syncthreads();

    float w0[4], w1[4], w2[4], bb[4], acc[4];
#pragma unroll
    for (int k = 0; k < 4; k++) {
        int h = tid + 256 * k;
        w0[k] = W[h]; w1[k] = W[HID + h]; w2[k] = W[2 * HID + h];
        bb[k] = B[h];
        acc[k] = 0.0f;
    }
#pragma unroll 4
    for (int p = 0; p < P; p++) {
        float x0 = sx0[p], x1 = sx1[p], x2 = sx2[p], y = sy[p];
#pragma unroll
        for (int k = 0; k < 4; k++) {
            float a = fmaf(x0, w0[k], fmaf(x1, w1[k], fmaf(x2, w2[k], bb[k])));
            acc[k] = fmaf(y, tanh_fast(a), acc[k]);
        }
    }
#pragma unroll
    for (int k = 0; k < 4; k++)
        g_part[mlp][sub][tid + 256 * k] = acc[k];
    if (tid == 0) {
        float s = 0.0f;
#pragma unroll
        for (int p = 0; p < P; p++) s += sy[p];
        g_ysum[mlp][sub] = s;
    }
}

// ---------------------------------------------------------------------------
// K2: Spart[hc][j] = sum_{h in chunk} t[h]*Wqb[h,j]  (+ ys*bqb[j] on hc==0)
// t-chunk is reduced from g_part in-block (L2-hot, 8K loads).
// grid: 256 blocks (2 MLPs x 16 h-chunks(64 rows) x 8 j-chunks(512 cols)),
// 128 threads, each thread one float4 column over 64 rows (unroll 8).
// ---------------------------------------------------------------------------
__global__ void k2_S(const float* __restrict__ Wq0b, const float* __restrict__ bq0b,
                     const float* __restrict__ Wq1b, const float* __restrict__ bq1b)
{
    const int blk = blockIdx.x;       // 0..255
    const int mlp = blk >> 7;
    const int rest = blk & 127;
    const int hc = rest >> 3;         // 0..15
    const int jc = rest & 7;          // 0..7
    const float* __restrict__ W = mlp ? Wq1b : Wq0b;
    const float* __restrict__ B = mlp ? bq1b : bq0b;
    const int tid = threadIdx.x;      // 0..127
    const int hbase = hc * 64;

    // ---- in-block t reduction: 2 threads per h, 64 subs each ----
    __shared__ float tp[2][64];
    __shared__ float t[64];
    __shared__ float sys;
    {
        const int hl = tid >> 1;      // 0..63
        const int half = tid & 1;
        float s = 0.0f;
#pragma unroll 16
        for (int b = 0; b < 64; b++)
            s += g_part[mlp][half * 64 + b][hbase + hl];
        tp[half][hl] = s;
    }
    if (hc == 0 && tid < 32) {
        float s = g_ysum[mlp][tid] + g_ysum[mlp][tid + 32] +
                  g_ysum[mlp][tid + 64] + g_ysum[mlp][tid + 96];
#pragma unroll
        for (int o = 16; o; o >>= 1) s += __shfl_xor_sync(0xffffffffu, s, o);
        if (tid == 0) sys = s;
    }
    __syncthreads();
    if (tid < 64) t[tid] = tp[0][tid] + tp[1][tid];
    __syncthreads();

    const int j0 = jc * 512 + tid * 4;
    float a0, a1, a2, a3;
    if (hc == 0) {
        float ys = sys;
        a0 = ys * B[j0]; a1 = ys * B[j0 + 1]; a2 = ys * B[j0 + 2]; a3 = ys * B[j0 + 3];
    } else {
        a0 = a1 = a2 = a3 = 0.0f;
    }
    const float4* __restrict__ W4 = (const float4*)W;
    const int col = j0 >> 2;
#pragma unroll 8
    for (int h = 0; h < 64; h++) {
        float th = t[h];
        float4 w = W4[(size_t)(hbase + h) * (RR / 4) + col];
        a0 = fmaf(th, w.x, a0);
        a1 = fmaf(th, w.y, a1);
        a2 = fmaf(th, w.z, a2);
        a3 = fmaf(th, w.w, a3);
    }
    *((float4*)&g_Spart[mlp][hc][j0]) = make_float4(a0, a1, a2, a3);
}

// ---------------------------------------------------------------------------
// K3: reduce g_Spart -> S0,S1 in smem;  r[b*64+d] = sum_x S0[b,x]*S1[d,x];
//     c = bx2 . r.   1 block, 1024 threads, float4 loads for the reduction.
// ---------------------------------------------------------------------------
__global__ void k3_rhs(const float* __restrict__ bx2)
{
    __shared__ float s0[64 * 65];
    __shared__ float s1[64 * 65];
    __shared__ float red[32];
    const int tid = threadIdx.x;   // 0..1023
    const float4* __restrict__ sp4 = (const float4*)g_Spart;

    // Phase A: reduce 16 hc-partials for both mlps (float4 per thread each)
#pragma unroll
    for (int m = 0; m < 2; m++) {
        float4 a = make_float4(0.f, 0.f, 0.f, 0.f);
#pragma unroll
        for (int hc = 0; hc < HC; hc++) {
            float4 w = sp4[(size_t)(m * HC + hc) * (RR / 4) + tid];
            a.x += w.x; a.y += w.y; a.z += w.z; a.w += w.w;
        }
        int b = tid >> 4;              // j = tid*4; row = j>>6
        int x = (tid & 15) * 4;        // col = j&63
        float* dst = (m ? s1 : s0) + b * 65 + x;
        dst[0] = a.x; dst[1] = a.y; dst[2] = a.z; dst[3] = a.w;
    }
    __syncthreads();

    // Phase B: r = S0 @ S1^T, fused bx2 dot
    float cacc = 0.0f;
#pragma unroll
    for (int k = 0; k < 4; k++) {
        int o = k * 1024 + tid;
        int b = o >> 6, d = o & 63;
        float acc = 0.0f;
#pragma unroll 16
        for (int x = 0; x < 64; x++)
            acc = fmaf(s0[b * 65 + x], s1[d * 65 + x], acc);
        g_r[o] = acc;
        cacc = fmaf(acc, bx2[o], cacc);
    }
#pragma unroll
    for (int o = 16; o; o >>= 1) cacc += __shfl_xor_sync(0xffffffffu, cacc, o);
    if ((tid & 31) == 0) red[tid >> 5] = cacc;
    __syncthreads();
    if (tid < 32) {
        float s = red[tid];
#pragma unroll
        for (int o = 16; o; o >>= 1) s += __shfl_xor_sync(0xffffffffu, s, o);
        if (tid == 0) g_c = s;
    }
}

// ---------------------------------------------------------------------------
// K4: v[h] = Wx2[h,:] . r.  grid: 512 blocks x 256 threads, 2 rows per block.
// ---------------------------------------------------------------------------
__global__ void k4_v(const float* __restrict__ Wx2)
{
    const int h0 = blockIdx.x * 2;
    const int tid = threadIdx.x;
    const float4* __restrict__ W4 = (const float4*)Wx2;
    const float4* __restrict__ r4 = (const float4*)g_r;
    const int c = tid * 4;        // float4 index, 4 per thread (1024 total)

    float a0 = 0.0f, a1 = 0.0f;
#pragma unroll
    for (int k = 0; k < 4; k++) {
        float4 rr = r4[c + k];
        float4 w0 = W4[(size_t)h0 * (RR / 4) + c + k];
        float4 w1 = W4[(size_t)(h0 + 1) * (RR / 4) + c + k];
        a0 = fmaf(w0.x, rr.x, a0); a0 = fmaf(w0.y, rr.y, a0);
        a0 = fmaf(w0.z, rr.z, a0); a0 = fmaf(w0.w, rr.w, a0);
        a1 = fmaf(w1.x, rr.x, a1); a1 = fmaf(w1.y, rr.y, a1);
        a1 = fmaf(w1.z, rr.z, a1); a1 = fmaf(w1.w, rr.w, a1);
    }
#pragma unroll
    for (int o = 16; o; o >>= 1) {
        a0 += __shfl_xor_sync(0xffffffffu, a0, o);
        a1 += __shfl_xor_sync(0xffffffffu, a1, o);
    }
    __shared__ float s0[8], s1[8];
    if ((tid & 31) == 0) { s0[tid >> 5] = a0; s1[tid >> 5] = a1; }
    __syncthreads();
    if (tid == 0) {
        float x = 0.0f, y = 0.0f;
#pragma unroll
        for (int i = 0; i < 8; i++) { x += s0[i]; y += s1[i]; }
        g_v[h0] = x;
        g_v[h0 + 1] = y;
    }
}

// ---------------------------------------------------------------------------
// K5: out[n] = tanh(input[n] @ Wx1 + bx1) . v + c
// grid: 512 blocks x 256 threads; warp handles 4 rows n (reuses smem loads 4x)
// ---------------------------------------------------------------------------
__global__ void k5_out(const float* __restrict__ input, const float* __restrict__ Wx1,
                       const float* __restrict__ bx1, float* __restrict__ out)
{
    __shared__ float4 swb[HID];   // (w0, w1, w2, bias)
    __shared__ float  sv[HID];
    const int tid = threadIdx.x;
#pragma unroll
    for (int k = 0; k < 4; k++) {
        int h = tid + 256 * k;
        swb[h] = make_float4(Wx1[h], Wx1[HID + h], Wx1[2 * HID + h], bx1[h]);
        sv[h] = g_v[h];
    }
    __syncthreads();

    const int warp = tid >> 5, lane = tid & 31;
    const int nbase = (blockIdx.x * 8 + warp) * 4;

    float x0[4], x1[4], x2[4];
#pragma unroll
    for (int nn = 0; nn < 4; nn++) {
        x0[nn] = input[(nbase + nn) * 3 + 0];
        x1[nn] = input[(nbase + nn) * 3 + 1];
        x2[nn] = input[(nbase + nn) * 3 + 2];
    }
    float acc[4] = {0.0f, 0.0f, 0.0f, 0.0f};
#pragma unroll 4
    for (int k = 0; k < 32; k++) {
        int h = k * 32 + lane;
        float4 wb = swb[h];
        float vv = sv[h];
#pragma unroll
        for (int nn = 0; nn < 4; nn++) {
            float a = fmaf(x0[nn], wb.x, fmaf(x1[nn], wb.y, fmaf(x2[nn], wb.z, wb.w)));
            acc[nn] = fmaf(tanh_fast(a), vv, acc[nn]);
        }
    }
    float c = g_c;
#pragma unroll
    for (int nn = 0; nn < 4; nn++) {
        float a = acc[nn];
#pragma unroll
        for (int o = 16; o; o >>= 1) a += __shfl_xor_sync(0xffffffffu, a, o);
        if (lane == 0) out[nbase + nn] = a + c;
    }
}

// ---------------------------------------------------------------------------
// Input order (metadata): 0 input, 1 eq_param, 2 quad_x0, 3 quad_x1,
// 4 Wx1, 5 bx1, 6 Wx2, 7 bx2, 8 Wq0a, 9 bq0a, 10 Wq0b, 11 bq0b,
// 12 Wq1a, 13 bq1a, 14 Wq1b, 15 bq1b
// ---------------------------------------------------------------------------
extern "C" void kernel_launch(void* const* d_in, const int* in_sizes, int n_in,
                              void* d_out, int out_size)
{
    const float* input  = (const float*)d_in[0];
    const float* eq     = (const float*)d_in[1];
    const float* qx0    = (const float*)d_in[2];
    const float* qx1    = (const float*)d_in[3];
    const float* Wx1    = (const float*)d_in[4];
    const float* bx1    = (const float*)d_in[5];
    const float* Wx2    = (const float*)d_in[6];
    const float* bx2    = (const float*)d_in[7];
    const float* Wq0a   = (const float*)d_in[8];
    const float* bq0a   = (const float*)d_in[9];
    const float* Wq0b   = (const float*)d_in[10];
    const float* bq0b   = (const float*)d_in[11];
    const float* Wq1a   = (const float*)d_in[12];
    const float* bq1a   = (const float*)d_in[13];
    const float* Wq1b   = (const float*)d_in[14];
    const float* bq1b   = (const float*)d_in[15];
    float* out = (float*)d_out;

    k1_quad<<<256, 256>>>(qx0, qx1, Wq0a, bq0a, Wq1a, bq1a, eq);
    k2_S<<<256, 128>>>(Wq0b, bq0b, Wq1b, bq1b);
    k3_rhs<<<1, 1024>>>(bx2);
    k4_v<<<512, 256>>>(Wx2);
    k5_out<<<512, 256>>>(input, Wx1, bx1, out);
}

// round 4
// speedup vs baseline: 1.3299x; 1.1105x over previous
#include <cuda_runtime.h>

// Problem constants
#define NQPTS 4096
#define HID   1024
#define RR    4096   // R*K = R*R = 64*64
#define NPTS  16384
#define SUBS  128    // k1 sub-blocks per MLP
#define HC    16     // k2 h-chunks (64 rows each)

// ---------------- scratch (device globals; no allocation allowed) ----------
__device__ __align__(16) float g_part[2][SUBS][HID]; // per-block partial t-sums
__device__ float g_ysum[2][SUBS];                    // per-block partial y-sums
__device__ __align__(16) float g_Spart[2][HC][RR];   // h-chunked partial S
__device__ __align__(16) float g_r[RR];              // rhs flattened [64*64]
__device__ __align__(16) float g_v[HID];             // Wx2 @ r
__device__ float g_c;                                // bx2 . r

__device__ __forceinline__ float tanh_fast(float x) {
    float y;
    asm("tanh.approx.f32 %0, %1;" : "=f"(y) : "f"(x));
    return y;
}

// ---------------------------------------------------------------------------
// K1: per quad point i: y_i = exp(-eq*||x||^2); accumulate
//     t[h] += y_i * tanh(x_i . W[:,h] + b[h]) into per-block partials.
// grid: 256 blocks (2 MLPs x 128 sub-blocks of 32 points), 256 threads.
// ---------------------------------------------------------------------------
__global__ void k1_quad(const float* __restrict__ qx0, const float* __restrict__ qx1,
                        const float* __restrict__ Wq0a, const float* __restrict__ bq0a,
                        const float* __restrict__ Wq1a, const float* __restrict__ bq1a,
                        const float* __restrict__ eq)
{
    const int blk = blockIdx.x;
    const int mlp = blk >> 7;
    const int sub = blk & (SUBS - 1);
    const float* __restrict__ qx = mlp ? qx1 : qx0;
    const float* __restrict__ W  = mlp ? Wq1a : Wq0a;
    const float* __restrict__ B  = mlp ? bq1a : bq0a;
    const int P = NQPTS / SUBS;         // 32 points per block
    const int base = sub * P;
    const int tid = threadIdx.x;

    __shared__ float sx0[32], sx1[32], sx2[32], sy[32];
    if (tid < P) {
        float x0 = qx[(base + tid) * 3 + 0];
        float x1 = qx[(base + tid) * 3 + 1];
        float x2 = qx[(base + tid) * 3 + 2];
        sx0[tid] = x0; sx1[tid] = x1; sx2[tid] = x2;
        sy[tid]  = __expf(-eq[0] * (x0 * x0 + x1 * x1 + x2 * x2));
    }
    __syncthreads();

    float w0[4], w1[4], w2[4], bb[4], acc[4];
#pragma unroll
    for (int k = 0; k < 4; k++) {
        int h = tid + 256 * k;
        w0[k] = W[h]; w1[k] = W[HID + h]; w2[k] = W[2 * HID + h];
        bb[k] = B[h];
        acc[k] = 0.0f;
    }
#pragma unroll 4
    for (int p = 0; p < P; p++) {
        float x0 = sx0[p], x1 = sx1[p], x2 = sx2[p], y = sy[p];
#pragma unroll
        for (int k = 0; k < 4; k++) {
            float a = fmaf(x0, w0[k], fmaf(x1, w1[k], fmaf(x2, w2[k], bb[k])));
            acc[k] = fmaf(y, tanh_fast(a), acc[k]);
        }
    }
#pragma unroll
    for (int k = 0; k < 4; k++)
        g_part[mlp][sub][tid + 256 * k] = acc[k];
    if (tid == 0) {
        float s = 0.0f;
#pragma unroll
        for (int p = 0; p < P; p++) s += sy[p];
        g_ysum[mlp][sub] = s;
    }
}

// ---------------------------------------------------------------------------
// K2: Spart[hc][j] = sum_{h in chunk} t[h]*Wqb[h,j]  (+ ys*bqb[j] on hc==0)
// t-chunk reduced from g_part in-block (L2-hot). Deep 16-wide load batches.
// grid: 256 blocks (2 MLPs x 16 h-chunks(64 rows) x 8 j-chunks(512 cols)),
// 128 threads, each thread one float4 column over 64 rows.
// ---------------------------------------------------------------------------
__global__ void __launch_bounds__(128)
k2_S(const float* __restrict__ Wq0b, const float* __restrict__ bq0b,
     const float* __restrict__ Wq1b, const float* __restrict__ bq1b)
{
    const int blk = blockIdx.x;       // 0..255
    const int mlp = blk >> 7;
    const int rest = blk & 127;
    const int hc = rest >> 3;         // 0..15
    const int jc = rest & 7;          // 0..7
    const float* __restrict__ W = mlp ? Wq1b : Wq0b;
    const float* __restrict__ B = mlp ? bq1b : bq0b;
    const int tid = threadIdx.x;      // 0..127
    const int hbase = hc * 64;

    // ---- in-block t reduction: 2 threads per h, 64 subs each ----
    __shared__ float tp[2][64];
    __shared__ float t[64];
    __shared__ float sys;
    {
        const int hl = tid >> 1;      // 0..63
        const int half = tid & 1;
        float s = 0.0f;
#pragma unroll 16
        for (int b = 0; b < 64; b++)
            s += g_part[mlp][half * 64 + b][hbase + hl];
        tp[half][hl] = s;
    }
    if (hc == 0 && tid < 32) {
        float s = g_ysum[mlp][tid] + g_ysum[mlp][tid + 32] +
                  g_ysum[mlp][tid + 64] + g_ysum[mlp][tid + 96];
#pragma unroll
        for (int o = 16; o; o >>= 1) s += __shfl_xor_sync(0xffffffffu, s, o);
        if (tid == 0) sys = s;
    }
    __syncthreads();
    if (tid < 64) t[tid] = tp[0][tid] + tp[1][tid];
    __syncthreads();

    const int j0 = jc * 512 + tid * 4;
    float a0, a1, a2, a3;
    if (hc == 0) {
        float ys = sys;
        a0 = ys * B[j0]; a1 = ys * B[j0 + 1]; a2 = ys * B[j0 + 2]; a3 = ys * B[j0 + 3];
    } else {
        a0 = a1 = a2 = a3 = 0.0f;
    }
    const float4* __restrict__ W4 = (const float4*)W + (size_t)hbase * (RR / 4) + (j0 >> 2);

    // 4 batches of 16 deep independent loads, then FMA
#pragma unroll
    for (int b = 0; b < 4; b++) {
        float4 w[16];
#pragma unroll
        for (int u = 0; u < 16; u++)
            w[u] = W4[(size_t)(b * 16 + u) * (RR / 4)];
#pragma unroll
        for (int u = 0; u < 16; u++) {
            float th = t[b * 16 + u];
            a0 = fmaf(th, w[u].x, a0);
            a1 = fmaf(th, w[u].y, a1);
            a2 = fmaf(th, w[u].z, a2);
            a3 = fmaf(th, w[u].w, a3);
        }
    }
    *((float4*)&g_Spart[mlp][hc][j0]) = make_float4(a0, a1, a2, a3);
}

// ---------------------------------------------------------------------------
// K3: reduce g_Spart -> S0,S1 in smem;  r[b*64+d] = sum_x S0[b,x]*S1[d,x];
//     c = bx2 . r.   1 block, 1024 threads, float4 loads for the reduction.
// ---------------------------------------------------------------------------
__global__ void k3_rhs(const float* __restrict__ bx2)
{
    __shared__ float s0[64 * 65];
    __shared__ float s1[64 * 65];
    __shared__ float red[32];
    const int tid = threadIdx.x;   // 0..1023
    const float4* __restrict__ sp4 = (const float4*)g_Spart;

    // Phase A: reduce 16 hc-partials for both mlps (float4 per thread each)
#pragma unroll
    for (int m = 0; m < 2; m++) {
        float4 a = make_float4(0.f, 0.f, 0.f, 0.f);
#pragma unroll
        for (int hc = 0; hc < HC; hc++) {
            float4 w = sp4[(size_t)(m * HC + hc) * (RR / 4) + tid];
            a.x += w.x; a.y += w.y; a.z += w.z; a.w += w.w;
        }
        int b = tid >> 4;              // j = tid*4; row = j>>6
        int x = (tid & 15) * 4;        // col = j&63
        float* dst = (m ? s1 : s0) + b * 65 + x;
        dst[0] = a.x; dst[1] = a.y; dst[2] = a.z; dst[3] = a.w;
    }
    __syncthreads();

    // Phase B: r = S0 @ S1^T, fused bx2 dot
    float cacc = 0.0f;
#pragma unroll
    for (int k = 0; k < 4; k++) {
        int o = k * 1024 + tid;
        int b = o >> 6, d = o & 63;
        float acc = 0.0f;
#pragma unroll 16
        for (int x = 0; x < 64; x++)
            acc = fmaf(s0[b * 65 + x], s1[d * 65 + x], acc);
        g_r[o] = acc;
        cacc = fmaf(acc, bx2[o], cacc);
    }
#pragma unroll
    for (int o = 16; o; o >>= 1) cacc += __shfl_xor_sync(0xffffffffu, cacc, o);
    if ((tid & 31) == 0) red[tid >> 5] = cacc;
    __syncthreads();
    if (tid < 32) {
        float s = red[tid];
#pragma unroll
        for (int o = 16; o; o >>= 1) s += __shfl_xor_sync(0xffffffffu, s, o);
        if (tid == 0) g_c = s;
    }
}

// ---------------------------------------------------------------------------
// K4: v[h] = Wx2[h,:] . r.  grid: 256 blocks x 256 threads, 4 rows per block.
// r staged in smem (shared by the 4 rows); W streamed as a 16-deep LDG.128
// batch per thread so ~8KB/warp is in flight (DRAM-rate).
// ---------------------------------------------------------------------------
__global__ void __launch_bounds__(256)
k4_v(const float* __restrict__ Wx2)
{
    __shared__ float4 sr[RR / 4];     // 16 KB
    const int tid = threadIdx.x;
    const float4* __restrict__ r4 = (const float4*)g_r;
#pragma unroll
    for (int k = 0; k < 4; k++)
        sr[tid + 256 * k] = r4[tid + 256 * k];
    __syncthreads();

    const int row = tid >> 6;                      // 0..3
    const int h = blockIdx.x * 4 + row;
    const int g = tid & 63;
    const float4* __restrict__ W4 = (const float4*)Wx2 + (size_t)h * (RR / 4) + g;

    float4 w[16];
#pragma unroll
    for (int k = 0; k < 16; k++)
        w[k] = W4[64 * k];
    float acc = 0.0f;
#pragma unroll
    for (int k = 0; k < 16; k++) {
        float4 rr = sr[g + 64 * k];
        acc = fmaf(w[k].x, rr.x, acc);
        acc = fmaf(w[k].y, rr.y, acc);
        acc = fmaf(w[k].z, rr.z, acc);
        acc = fmaf(w[k].w, rr.w, acc);
    }
#pragma unroll
    for (int o = 16; o; o >>= 1) acc += __shfl_xor_sync(0xffffffffu, acc, o);
    __shared__ float part[8];
    if ((tid & 31) == 0) part[tid >> 5] = acc;
    __syncthreads();
    if (tid < 4)
        g_v[blockIdx.x * 4 + tid] = part[2 * tid] + part[2 * tid + 1];
}

// ---------------------------------------------------------------------------
// K5: out[n] = tanh(input[n] @ Wx1 + bx1) . v + c
// grid: 512 blocks x 256 threads; warp handles 4 rows n (reuses smem loads 4x)
// ---------------------------------------------------------------------------
__global__ void k5_out(const float* __restrict__ input, const float* __restrict__ Wx1,
                       const float* __restrict__ bx1, float* __restrict__ out)
{
    __shared__ float4 swb[HID];   // (w0, w1, w2, bias)
    __shared__ float  sv[HID];
    const int tid = threadIdx.x;
#pragma unroll
    for (int k = 0; k < 4; k++) {
        int h = tid + 256 * k;
        swb[h] = make_float4(Wx1[h], Wx1[HID + h], Wx1[2 * HID + h], bx1[h]);
        sv[h] = g_v[h];
    }
    __syncthreads();

    const int warp = tid >> 5, lane = tid & 31;
    const int nbase = (blockIdx.x * 8 + warp) * 4;

    float x0[4], x1[4], x2[4];
#pragma unroll
    for (int nn = 0; nn < 4; nn++) {
        x0[nn] = input[(nbase + nn) * 3 + 0];
        x1[nn] = input[(nbase + nn) * 3 + 1];
        x2[nn] = input[(nbase + nn) * 3 + 2];
    }
    float acc[4] = {0.0f, 0.0f, 0.0f, 0.0f};
#pragma unroll 4
    for (int k = 0; k < 32; k++) {
        int h = k * 32 + lane;
        float4 wb = swb[h];
        float vv = sv[h];
#pragma unroll
        for (int nn = 0; nn < 4; nn++) {
            float a = fmaf(x0[nn], wb.x, fmaf(x1[nn], wb.y, fmaf(x2[nn], wb.z, wb.w)));
            acc[nn] = fmaf(tanh_fast(a), vv, acc[nn]);
        }
    }
    float c = g_c;
#pragma unroll
    for (int nn = 0; nn < 4; nn++) {
        float a = acc[nn];
#pragma unroll
        for (int o = 16; o; o >>= 1) a += __shfl_xor_sync(0xffffffffu, a, o);
        if (lane == 0) out[nbase + nn] = a + c;
    }
}

// ---------------------------------------------------------------------------
// Input order (metadata): 0 input, 1 eq_param, 2 quad_x0, 3 quad_x1,
// 4 Wx1, 5 bx1, 6 Wx2, 7 bx2, 8 Wq0a, 9 bq0a, 10 Wq0b, 11 bq0b,
// 12 Wq1a, 13 bq1a, 14 Wq1b, 15 bq1b
// ---------------------------------------------------------------------------
extern "C" void kernel_launch(void* const* d_in, const int* in_sizes, int n_in,
                              void* d_out, int out_size)
{
    const float* input  = (const float*)d_in[0];
    const float* eq     = (const float*)d_in[1];
    const float* qx0    = (const float*)d_in[2];
    const float* qx1    = (const float*)d_in[3];
    const float* Wx1    = (const float*)d_in[4];
    const float* bx1    = (const float*)d_in[5];
    const float* Wx2    = (const float*)d_in[6];
    const float* bx2    = (const float*)d_in[7];
    const float* Wq0a   = (const float*)d_in[8];
    const float* bq0a   = (const float*)d_in[9];
    const float* Wq0b   = (const float*)d_in[10];
    const float* bq0b   = (const float*)d_in[11];
    const float* Wq1a   = (const float*)d_in[12];
    const float* bq1a   = (const float*)d_in[13];
    const float* Wq1b   = (const float*)d_in[14];
    const float* bq1b   = (const float*)d_in[15];
    float* out = (float*)d_out;

    k1_quad<<<256, 256>>>(qx0, qx1, Wq0a, bq0a, Wq1a, bq1a, eq);
    k2_S<<<256, 128>>>(Wq0b, bq0b, Wq1b, bq1b);
    k3_rhs<<<1, 1024>>>(bx2);
    k4_v<<<256, 256>>>(Wx2);
    k5_out<<<512, 256>>>(input, Wx1, bx1, out);
}

// round 5
// speedup vs baseline: 1.6888x; 1.2699x over previous
#include <cuda_runtime.h>

// Problem constants
#define NQPTS 4096
#define HID   1024
#define RR    4096   // R*K = R*R = 64*64
#define NPTS  16384
#define SUBS  128    // k1 sub-blocks per MLP
#define HC2   32     // k2 h-chunks (32 rows each)

// ---------------- scratch (device globals; no allocation allowed) ----------
__device__ __align__(16) float g_part[2][SUBS][HID]; // per-block partial t-sums
__device__ float g_ysum[2][SUBS];                    // per-block partial y-sums
__device__ __align__(16) float g_Spart[2][HC2][RR];  // h-chunked partial S
__device__ __align__(16) float g_S[2][RR];           // reduced S0, S1
__device__ __align__(16) float g_r[RR];              // rhs flattened [64*64]
__device__ __align__(16) float g_v[HID];             // Wx2 @ r
__device__ float g_c;                                // bx2 . r

__device__ __forceinline__ float tanh_fast(float x) {
    float y;
    asm("tanh.approx.f32 %0, %1;" : "=f"(y) : "f"(x));
    return y;
}

// Forced-order loads: volatile asm pins issue order -> guaranteed deep MLP.
__device__ __forceinline__ float4 ldg4(const float4* p) {
    float4 v;
    asm volatile("ld.global.nc.v4.f32 {%0,%1,%2,%3}, [%4];"
                 : "=f"(v.x), "=f"(v.y), "=f"(v.z), "=f"(v.w) : "l"(p));
    return v;
}
__device__ __forceinline__ float ldgf(const float* p) {
    float v;
    asm volatile("ld.global.nc.f32 %0, [%1];" : "=f"(v) : "l"(p));
    return v;
}

// ---------------------------------------------------------------------------
// K1: per quad point i: y_i = exp(-eq*||x||^2); accumulate
//     t[h] += y_i * tanh(x_i . W[:,h] + b[h]) into per-block partials.
// grid: 256 blocks (2 MLPs x 128 sub-blocks of 32 points), 256 threads.
// ---------------------------------------------------------------------------
__global__ void k1_quad(const float* __restrict__ qx0, const float* __restrict__ qx1,
                        const float* __restrict__ Wq0a, const float* __restrict__ bq0a,
                        const float* __restrict__ Wq1a, const float* __restrict__ bq1a,
                        const float* __restrict__ eq)
{
    const int blk = blockIdx.x;
    const int mlp = blk >> 7;
    const int sub = blk & (SUBS - 1);
    const float* __restrict__ qx = mlp ? qx1 : qx0;
    const float* __restrict__ W  = mlp ? Wq1a : Wq0a;
    const float* __restrict__ B  = mlp ? bq1a : bq0a;
    const int P = NQPTS / SUBS;         // 32 points per block
    const int base = sub * P;
    const int tid = threadIdx.x;

    __shared__ float sx0[32], sx1[32], sx2[32], sy[32];
    if (tid < P) {
        float x0 = qx[(base + tid) * 3 + 0];
        float x1 = qx[(base + tid) * 3 + 1];
        float x2 = qx[(base + tid) * 3 + 2];
        sx0[tid] = x0; sx1[tid] = x1; sx2[tid] = x2;
        sy[tid]  = __expf(-eq[0] * (x0 * x0 + x1 * x1 + x2 * x2));
    }
    __syncthreads();

    float w0[4], w1[4], w2[4], bb[4], acc[4];
#pragma unroll
    for (int k = 0; k < 4; k++) {
        int h = tid + 256 * k;
        w0[k] = W[h]; w1[k] = W[HID + h]; w2[k] = W[2 * HID + h];
        bb[k] = B[h];
        acc[k] = 0.0f;
    }
#pragma unroll 4
    for (int p = 0; p < P; p++) {
        float x0 = sx0[p], x1 = sx1[p], x2 = sx2[p], y = sy[p];
#pragma unroll
        for (int k = 0; k < 4; k++) {
            float a = fmaf(x0, w0[k], fmaf(x1, w1[k], fmaf(x2, w2[k], bb[k])));
            acc[k] = fmaf(y, tanh_fast(a), acc[k]);
        }
    }
#pragma unroll
    for (int k = 0; k < 4; k++)
        g_part[mlp][sub][tid + 256 * k] = acc[k];
    if (tid == 0) {
        float s = 0.0f;
#pragma unroll
        for (int p = 0; p < P; p++) s += sy[p];
        g_ysum[mlp][sub] = s;
    }
}

// ---------------------------------------------------------------------------
// K2: Spart[hc][j] = sum_{h in 32-row chunk} t[h]*Wqb[h,j] (+ ys*bqb[j] hc==0)
// grid: 512 blocks (2 MLPs x 32 h-chunks x 8 j-chunks(512 cols)), 128 thr.
// Forced 8-deep LDG.128 batches for the W stream.
// ---------------------------------------------------------------------------
__global__ void __launch_bounds__(128)
k2_S(const float* __restrict__ Wq0b, const float* __restrict__ bq0b,
     const float* __restrict__ Wq1b, const float* __restrict__ bq1b)
{
    const int blk = blockIdx.x;       // 0..511
    const int mlp = blk >> 8;
    const int rest = blk & 255;
    const int hc = rest >> 3;         // 0..31 (32 rows each)
    const int jc = rest & 7;          // 0..7  (512 cols each)
    const float* __restrict__ W = mlp ? Wq1b : Wq0b;
    const float* __restrict__ B = mlp ? bq1b : bq0b;
    const int tid = threadIdx.x;      // 0..127
    const int hbase = hc * 32;

    __shared__ float tp[4][32];
    __shared__ float t[32];
    __shared__ float sys;

    // ---- t reduction: 4 threads per h, 32 subs each, forced 8-deep loads ---
    {
        const int q = tid >> 5;       // 0..3
        const int h = tid & 31;
        const float* p = &g_part[mlp][q * 32][hbase + h];
        float s = 0.0f;
#pragma unroll
        for (int b = 0; b < 4; b++) {
            float v[8];
#pragma unroll
            for (int u = 0; u < 8; u++)
                v[u] = ldgf(p + (size_t)(b * 8 + u) * HID);
#pragma unroll
            for (int u = 0; u < 8; u++) s += v[u];
        }
        tp[q][h] = s;
    }
    __syncthreads();
    if (tid < 32) t[tid] = tp[0][tid] + tp[1][tid] + tp[2][tid] + tp[3][tid];
    if (hc == 0 && tid >= 64 && tid < 96) {
        int l = tid - 64;
        float s = g_ysum[mlp][l] + g_ysum[mlp][l + 32] +
                  g_ysum[mlp][l + 64] + g_ysum[mlp][l + 96];
#pragma unroll
        for (int o = 16; o; o >>= 1) s += __shfl_xor_sync(0xffffffffu, s, o);
        if (l == 0) sys = s;
    }
    __syncthreads();

    const int j0 = jc * 512 + tid * 4;
    float a0, a1, a2, a3;
    if (hc == 0) {
        float ys = sys;
        a0 = ys * B[j0]; a1 = ys * B[j0 + 1]; a2 = ys * B[j0 + 2]; a3 = ys * B[j0 + 3];
    } else {
        a0 = a1 = a2 = a3 = 0.0f;
    }
    const float4* __restrict__ W4 =
        (const float4*)W + (size_t)hbase * (RR / 4) + (j0 >> 2);

#pragma unroll
    for (int b = 0; b < 4; b++) {
        float4 w[8];
#pragma unroll
        for (int u = 0; u < 8; u++)
            w[u] = ldg4(W4 + (size_t)(b * 8 + u) * (RR / 4));
#pragma unroll
        for (int u = 0; u < 8; u++) {
            float th = t[b * 8 + u];
            a0 = fmaf(th, w[u].x, a0);
            a1 = fmaf(th, w[u].y, a1);
            a2 = fmaf(th, w[u].z, a2);
            a3 = fmaf(th, w[u].w, a3);
        }
    }
    *((float4*)&g_Spart[mlp][hc][j0]) = make_float4(a0, a1, a2, a3);
}

// ---------------------------------------------------------------------------
// K2b: reduce g_Spart (32 chunks) -> g_S.  16 blocks x 128 threads,
// one float4 output per thread, forced 8-deep loads.
// ---------------------------------------------------------------------------
__global__ void __launch_bounds__(128)
k2b_reduce()
{
    const int j4 = blockIdx.x * 128 + threadIdx.x;   // 0..2047
    const int mlp = j4 >> 10;
    const int col = j4 & 1023;
    const float4* __restrict__ base =
        (const float4*)g_Spart + (size_t)mlp * HC2 * (RR / 4) + col;
    float4 a = make_float4(0.f, 0.f, 0.f, 0.f);
#pragma unroll
    for (int b = 0; b < 4; b++) {
        float4 v[8];
#pragma unroll
        for (int u = 0; u < 8; u++)
            v[u] = ldg4(base + (size_t)(b * 8 + u) * (RR / 4));
#pragma unroll
        for (int u = 0; u < 8; u++) {
            a.x += v[u].x; a.y += v[u].y; a.z += v[u].z; a.w += v[u].w;
        }
    }
    ((float4*)g_S)[j4] = a;
}

// ---------------------------------------------------------------------------
// K3: r[b*64+d] = sum_x S0[b,x]*S1[d,x].  16 blocks x 256 threads,
// each block: 4 b-rows x 64 d. S1 staged padded; S0 4 rows staged.
// ---------------------------------------------------------------------------
__global__ void k3_rhs()
{
    __shared__ float s1[64 * 65];
    __shared__ float s0[4 * 65];
    const int tid = threadIdx.x;   // 0..255
    const int bbase = blockIdx.x * 4;

    // stage S1 (full, padded pitch 65)
#pragma unroll
    for (int k = 0; k < 16; k++) {
        int j = k * 256 + tid;
        s1[(j >> 6) * 65 + (j & 63)] = g_S[1][j];
    }
    // stage S0 rows bbase..bbase+3
    if (tid < 256) {
        int b = tid >> 6, x = tid & 63;
        s0[b * 65 + x] = g_S[0][(bbase + b) * 64 + x];
    }
    __syncthreads();

    const int b = tid >> 6;        // 0..3
    const int d = tid & 63;
    float acc = 0.0f;
#pragma unroll 16
    for (int x = 0; x < 64; x++)
        acc = fmaf(s0[b * 65 + x], s1[d * 65 + x], acc);
    g_r[(bbase + b) * 64 + d] = acc;
}

// ---------------------------------------------------------------------------
// K4: v[h] = Wx2[h,:] . r  (blocks 0..511, 2 rows each, r staged in smem,
// forced 8-deep W batches).  Block 512 computes c = bx2 . r.
// ---------------------------------------------------------------------------
__global__ void __launch_bounds__(256)
k4_v(const float* __restrict__ Wx2, const float* __restrict__ bx2)
{
    const int tid = threadIdx.x;

    if (blockIdx.x == 512) {    // c = bx2 . r
        const float4* __restrict__ b4 = (const float4*)bx2;
        const float4* __restrict__ r4 = (const float4*)g_r;
        float acc = 0.0f;
#pragma unroll
        for (int k = 0; k < 4; k++) {
            float4 b = ldg4(b4 + tid + 256 * k);
            float4 r = ldg4(r4 + tid + 256 * k);
            acc += b.x * r.x + b.y * r.y + b.z * r.z + b.w * r.w;
        }
#pragma unroll
        for (int o = 16; o; o >>= 1) acc += __shfl_xor_sync(0xffffffffu, acc, o);
        __shared__ float red[8];
        if ((tid & 31) == 0) red[tid >> 5] = acc;
        __syncthreads();
        if (tid == 0) {
            float s = 0.0f;
#pragma unroll
            for (int i = 0; i < 8; i++) s += red[i];
            g_c = s;
        }
        return;
    }

    __shared__ float4 sr[RR / 4];     // 16 KB
    const float4* __restrict__ r4 = (const float4*)g_r;
#pragma unroll
    for (int k = 0; k < 4; k++)
        sr[tid + 256 * k] = r4[tid + 256 * k];
    __syncthreads();

    const int row = tid >> 7;                      // 0 or 1
    const int h = blockIdx.x * 2 + row;
    const int g = tid & 127;
    const float4* __restrict__ W4 = (const float4*)Wx2 + (size_t)h * (RR / 4) + g;

    float4 w[8];
#pragma unroll
    for (int k = 0; k < 8; k++)
        w[k] = ldg4(W4 + 128 * k);
    float acc = 0.0f;
#pragma unroll
    for (int k = 0; k < 8; k++) {
        float4 rr = sr[g + 128 * k];
        acc = fmaf(w[k].x, rr.x, acc);
        acc = fmaf(w[k].y, rr.y, acc);
        acc = fmaf(w[k].z, rr.z, acc);
        acc = fmaf(w[k].w, rr.w, acc);
    }
#pragma unroll
    for (int o = 16; o; o >>= 1) acc += __shfl_xor_sync(0xffffffffu, acc, o);
    __shared__ float part[8];
    if ((tid & 31) == 0) part[tid >> 5] = acc;
    __syncthreads();
    if (tid < 2)
        g_v[blockIdx.x * 2 + tid] = part[4 * tid] + part[4 * tid + 1] +
                                    part[4 * tid + 2] + part[4 * tid + 3];
}

// ---------------------------------------------------------------------------
// K5: out[n] = tanh(input[n] @ Wx1 + bx1) . v + c
// grid: 512 blocks x 256 threads; warp handles 4 rows n (reuses smem loads 4x)
// ---------------------------------------------------------------------------
__global__ void k5_out(const float* __restrict__ input, const float* __restrict__ Wx1,
                       const float* __restrict__ bx1, float* __restrict__ out)
{
    __shared__ float4 swb[HID];   // (w0, w1, w2, bias)
    __shared__ float  sv[HID];
    const int tid = threadIdx.x;
#pragma unroll
    for (int k = 0; k < 4; k++) {
        int h = tid + 256 * k;
        swb[h] = make_float4(Wx1[h], Wx1[HID + h], Wx1[2 * HID + h], bx1[h]);
        sv[h] = g_v[h];
    }
    __syncthreads();

    const int warp = tid >> 5, lane = tid & 31;
    const int nbase = (blockIdx.x * 8 + warp) * 4;

    float x0[4], x1[4], x2[4];
#pragma unroll
    for (int nn = 0; nn < 4; nn++) {
        x0[nn] = input[(nbase + nn) * 3 + 0];
        x1[nn] = input[(nbase + nn) * 3 + 1];
        x2[nn] = input[(nbase + nn) * 3 + 2];
    }
    float acc[4] = {0.0f, 0.0f, 0.0f, 0.0f};
#pragma unroll 4
    for (int k = 0; k < 32; k++) {
        int h = k * 32 + lane;
        float4 wb = swb[h];
        float vv = sv[h];
#pragma unroll
        for (int nn = 0; nn < 4; nn++) {
            float a = fmaf(x0[nn], wb.x, fmaf(x1[nn], wb.y, fmaf(x2[nn], wb.z, wb.w)));
            acc[nn] = fmaf(tanh_fast(a), vv, acc[nn]);
        }
    }
    float c = g_c;
#pragma unroll
    for (int nn = 0; nn < 4; nn++) {
        float a = acc[nn];
#pragma unroll
        for (int o = 16; o; o >>= 1) a += __shfl_xor_sync(0xffffffffu, a, o);
        if (lane == 0) out[nbase + nn] = a + c;
    }
}

// ---------------------------------------------------------------------------
// Input order (metadata): 0 input, 1 eq_param, 2 quad_x0, 3 quad_x1,
// 4 Wx1, 5 bx1, 6 Wx2, 7 bx2, 8 Wq0a, 9 bq0a, 10 Wq0b, 11 bq0b,
// 12 Wq1a, 13 bq1a, 14 Wq1b, 15 bq1b
// ---------------------------------------------------------------------------
extern "C" void kernel_launch(void* const* d_in, const int* in_sizes, int n_in,
                              void* d_out, int out_size)
{
    const float* input  = (const float*)d_in[0];
    const float* eq     = (const float*)d_in[1];
    const float* qx0    = (const float*)d_in[2];
    const float* qx1    = (const float*)d_in[3];
    const float* Wx1    = (const float*)d_in[4];
    const float* bx1    = (const float*)d_in[5];
    const float* Wx2    = (const float*)d_in[6];
    const float* bx2    = (const float*)d_in[7];
    const float* Wq0a   = (const float*)d_in[8];
    const float* bq0a   = (const float*)d_in[9];
    const float* Wq0b   = (const float*)d_in[10];
    const float* bq0b   = (const float*)d_in[11];
    const float* Wq1a   = (const float*)d_in[12];
    const float* bq1a   = (const float*)d_in[13];
    const float* Wq1b   = (const float*)d_in[14];
    const float* bq1b   = (const float*)d_in[15];
    float* out = (float*)d_out;

    k1_quad<<<256, 256>>>(qx0, qx1, Wq0a, bq0a, Wq1a, bq1a, eq);
    k2_S<<<512, 128>>>(Wq0b, bq0b, Wq1b, bq1b);
    k2b_reduce<<<16, 128>>>();
    k3_rhs<<<16, 256>>>();
    k4_v<<<513, 256>>>(Wx2, bx2);
    k5_out<<<512, 256>>>(input, Wx1, bx1, out);
}